// round 1
// baseline (speedup 1.0000x reference)
#include <cuda_runtime.h>
#include <cuda_bf16.h>

// Shapes (fixed by the problem)
#define SEQ   192
#define BATCH 2
#define C_P   128
#define C     32
#define C_I   128

// Scratch (device globals: no allocation allowed in kernel_launch)
__device__ float g_p1t[BATCH * C * SEQ];          // [b][c][s]
__device__ float g_p2t[BATCH * C * SEQ];          // [b][d][s]
__device__ float g_M[BATCH * C_I * C * SEQ];      // [b][k][c][j]  (6.29 MB)

// ---------------------------------------------------------------------------
// Kernel 1: LayerNorm over C_P + dual projections (W1,b1)->p1t, (W2,b2)->p2t
// grid = SEQ*BATCH blocks, 128 threads each
// ---------------------------------------------------------------------------
__global__ void k1_ln_proj(const float* __restrict__ p,
                           const float* __restrict__ gamma,
                           const float* __restrict__ beta,
                           const float* __restrict__ W1,
                           const float* __restrict__ b1,
                           const float* __restrict__ W2,
                           const float* __restrict__ b2) {
    const int r = blockIdx.x;            // row index over (s,b)
    const int s = r / BATCH;
    const int b = r % BATCH;
    const int tid = threadIdx.x;         // 0..127 == channel p

    float x = p[r * C_P + tid];

    // block reduction for sum and sumsq
    float s1 = x, s2 = x * x;
    #pragma unroll
    for (int off = 16; off > 0; off >>= 1) {
        s1 += __shfl_down_sync(0xFFFFFFFFu, s1, off);
        s2 += __shfl_down_sync(0xFFFFFFFFu, s2, off);
    }
    __shared__ float a1[4], a2[4];
    const int warp = tid >> 5, lane = tid & 31;
    if (lane == 0) { a1[warp] = s1; a2[warp] = s2; }
    __syncthreads();
    float sum  = a1[0] + a1[1] + a1[2] + a1[3];
    float sumq = a2[0] + a2[1] + a2[2] + a2[3];

    const float inv = 1.0f / (float)C_P;
    float mu  = sum * inv;
    float var = sumq * inv - mu * mu;
    float rstd = rsqrtf(var + 1e-5f);

    __shared__ float sh_pn[C_P];
    sh_pn[tid] = (x - mu) * rstd * gamma[tid] + beta[tid];
    __syncthreads();

    if (tid < 64) {
        const int   c   = tid & 31;
        const bool  one = (tid < 32);
        const float* W  = one ? W1 : W2;
        const float* bb = one ? b1 : b2;
        float*       dst = one ? g_p1t : g_p2t;

        float acc = bb[c];
        const float4* w4  = (const float4*)(W + c * C_P);
        const float4* pn4 = (const float4*)sh_pn;
        #pragma unroll
        for (int q = 0; q < C_P / 4; ++q) {
            float4 w = w4[q];
            float4 v = pn4[q];
            acc += w.x * v.x + w.y * v.y + w.z * v.z + w.w * v.w;
        }
        dst[(b * C + c) * SEQ + s] = acc;
    }
}

// ---------------------------------------------------------------------------
// Kernel 2: M[b,k,c,j] = sum_d p2[b,j,d] * Wout[k, c*C + d]
// grid = BATCH*C_I blocks, SEQ threads each
// ---------------------------------------------------------------------------
__global__ void k2_build_M(const float* __restrict__ Wout) {
    const int bk = blockIdx.x;           // b*C_I + k
    const int b  = bk >> 7;
    const int k  = bk & (C_I - 1);
    const int j  = threadIdx.x;          // 0..191

    __shared__ float shW[C * C];         // 1024 floats = Wout row k
    for (int t = j; t < C * C; t += SEQ) shW[t] = Wout[k * (C * C) + t];

    float q[C];
    #pragma unroll
    for (int d = 0; d < C; ++d) q[d] = g_p2t[(b * C + d) * SEQ + j];
    __syncthreads();

    float* dst = g_M + (size_t)bk * C * SEQ;
    #pragma unroll
    for (int c = 0; c < C; ++c) {
        const float4* w4 = (const float4*)(shW + c * C);
        float acc = 0.0f;
        #pragma unroll
        for (int d4 = 0; d4 < C / 4; ++d4) {
            float4 w = w4[d4];
            acc += q[d4 * 4 + 0] * w.x + q[d4 * 4 + 1] * w.y
                 + q[d4 * 4 + 2] * w.z + q[d4 * 4 + 3] * w.w;
        }
        dst[c * SEQ + j] = acc;
    }
}

// ---------------------------------------------------------------------------
// Kernel 3: out[b,k,i,j] = (sum_c p1t[b,c,i] * M[b,k,c,j] + bout[k]) / BATCH
// grid = BATCH*C_I blocks; 16x16 threads; 12x12 register tile per thread
// ---------------------------------------------------------------------------
__global__ __launch_bounds__(256, 1)
void k3_gemm(const float* __restrict__ bout, float* __restrict__ out) {
    const int bk = blockIdx.x;
    const int b  = bk >> 7;
    const int k  = bk & (C_I - 1);

    __shared__ float As[C][SEQ];         // p1t[b]   : 24 KB
    __shared__ float Bs[C][SEQ];         // M[b][k]  : 24 KB

    const int tid = threadIdx.x;
    {
        const float4* Ap = (const float4*)(g_p1t + (size_t)b * C * SEQ);
        const float4* Bp = (const float4*)(g_M + (size_t)bk * C * SEQ);
        float4* As4 = (float4*)As;
        float4* Bs4 = (float4*)Bs;
        #pragma unroll
        for (int t = tid; t < C * SEQ / 4; t += 256) {
            As4[t] = Ap[t];
            Bs4[t] = Bp[t];
        }
    }
    __syncthreads();

    const int tx = tid & 15;
    const int ty = tid >> 4;
    const int i0 = ty * 12;
    const int j0 = tx * 12;

    float acc[12][12];
    #pragma unroll
    for (int i = 0; i < 12; ++i)
        #pragma unroll
        for (int j = 0; j < 12; ++j) acc[i][j] = 0.0f;

    #pragma unroll
    for (int kk = 0; kk < C; ++kk) {
        float a[12], bb[12];
        #pragma unroll
        for (int q = 0; q < 3; ++q) {
            float4 av = *(const float4*)&As[kk][i0 + q * 4];
            a[q * 4 + 0] = av.x; a[q * 4 + 1] = av.y;
            a[q * 4 + 2] = av.z; a[q * 4 + 3] = av.w;
            float4 bv = *(const float4*)&Bs[kk][j0 + q * 4];
            bb[q * 4 + 0] = bv.x; bb[q * 4 + 1] = bv.y;
            bb[q * 4 + 2] = bv.z; bb[q * 4 + 3] = bv.w;
        }
        #pragma unroll
        for (int i = 0; i < 12; ++i)
            #pragma unroll
            for (int j = 0; j < 12; ++j)
                acc[i][j] += a[i] * bb[j];
    }

    const float bias = bout[k];
    const float scale = 1.0f / (float)BATCH;
    float* obase = out + ((size_t)bk * SEQ) * SEQ;
    #pragma unroll
    for (int i = 0; i < 12; ++i) {
        float* orow = obase + (size_t)(i0 + i) * SEQ + j0;
        #pragma unroll
        for (int q = 0; q < 3; ++q) {
            float4 v;
            v.x = (acc[i][q * 4 + 0] + bias) * scale;
            v.y = (acc[i][q * 4 + 1] + bias) * scale;
            v.z = (acc[i][q * 4 + 2] + bias) * scale;
            v.w = (acc[i][q * 4 + 3] + bias) * scale;
            *(float4*)(orow + q * 4) = v;
        }
    }
}

// ---------------------------------------------------------------------------
extern "C" void kernel_launch(void* const* d_in, const int* in_sizes, int n_in,
                              void* d_out, int out_size) {
    const float* p     = (const float*)d_in[0];
    const float* gamma = (const float*)d_in[1];
    const float* beta  = (const float*)d_in[2];
    const float* W1    = (const float*)d_in[3];
    const float* b1    = (const float*)d_in[4];
    const float* W2    = (const float*)d_in[5];
    const float* b2    = (const float*)d_in[6];
    const float* Wout  = (const float*)d_in[7];
    const float* bout  = (const float*)d_in[8];
    float* out = (float*)d_out;

    k1_ln_proj<<<SEQ * BATCH, C_P>>>(p, gamma, beta, W1, b1, W2, b2);
    k2_build_M<<<BATCH * C_I, SEQ>>>(Wout);
    k3_gemm<<<BATCH * C_I, 256>>>(bout, out);
}

// round 2
// speedup vs baseline: 1.0557x; 1.0557x over previous
#include <cuda_runtime.h>
#include <cuda_bf16.h>

// Shapes (fixed by the problem)
#define SEQ   192
#define BATCH 2
#define C_P   128
#define C     32
#define C_I   128

// Cross-kernel scratch (device globals: no allocation allowed)
__device__ float g_p1t[BATCH * C * SEQ];          // [b][c][s]
__device__ float g_p2t[BATCH * C * SEQ];          // [b][d][s]

// ---- packed fp32x2 helpers (Blackwell FFMA2) --------------------------------
#define FMA_F32X2(d, a, b, c) \
    asm("fma.rn.f32x2 %0, %1, %2, %3;" : "=l"(d) : "l"(a), "l"(b), "l"(c))
#define PACK_F32X2(out, lo, hi) \
    asm("mov.b64 %0, {%1, %2};" : "=l"(out) : "r"(__float_as_uint(lo)), "r"(__float_as_uint(hi)))
#define UNPACK_F32X2(lo, hi, in) \
    do { unsigned int _l, _h; \
         asm("mov.b64 {%0, %1}, %2;" : "=r"(_l), "=r"(_h) : "l"(in)); \
         lo = __uint_as_float(_l); hi = __uint_as_float(_h); } while (0)

// ---------------------------------------------------------------------------
// Kernel 1: LayerNorm over C_P + dual projections -> transposed p1t/p2t
// grid = SEQ*BATCH blocks, 128 threads. All 128 threads split the 64 dots
// (2 threads per output, 64 elems each, 4 accumulators) to kill latency.
// ---------------------------------------------------------------------------
__global__ __launch_bounds__(128)
void k1_ln_proj(const float* __restrict__ p,
                const float* __restrict__ gamma,
                const float* __restrict__ beta,
                const float* __restrict__ W1,
                const float* __restrict__ b1,
                const float* __restrict__ W2,
                const float* __restrict__ b2) {
    const int r = blockIdx.x;            // row over (s,b)
    const int s = r / BATCH;
    const int b = r % BATCH;
    const int tid = threadIdx.x;         // 0..127

    float x = p[r * C_P + tid];

    // block reduction for sum / sumsq
    float s1 = x, s2 = x * x;
    #pragma unroll
    for (int off = 16; off > 0; off >>= 1) {
        s1 += __shfl_down_sync(0xFFFFFFFFu, s1, off);
        s2 += __shfl_down_sync(0xFFFFFFFFu, s2, off);
    }
    __shared__ float a1[4], a2[4];
    const int warp = tid >> 5, lane = tid & 31;
    if (lane == 0) { a1[warp] = s1; a2[warp] = s2; }
    __syncthreads();
    float sum  = a1[0] + a1[1] + a1[2] + a1[3];
    float sumq = a2[0] + a2[1] + a2[2] + a2[3];

    const float inv = 1.0f / (float)C_P;
    float mu   = sum * inv;
    float var  = sumq * inv - mu * mu;
    float rstd = rsqrtf(var + 1e-5f);

    __shared__ float sh_pn[C_P];
    sh_pn[tid] = (x - mu) * rstd * gamma[tid] + beta[tid];
    __syncthreads();

    // projection: output o = tid&63 (o<32 -> W1 row o, else W2 row o-32),
    // half h = tid>>6 covers channels [h*64, h*64+64)
    const int  o = tid & 63;
    const int  h = tid >> 6;
    const int  c = (o < 32) ? o : (o - 32);
    const float* W = (o < 32) ? W1 : W2;

    const float4* w4  = (const float4*)(W + c * C_P + h * 64);
    const float4* pn4 = (const float4*)(sh_pn + h * 64);
    float acc0 = 0.f, acc1 = 0.f, acc2 = 0.f, acc3 = 0.f;
    #pragma unroll
    for (int q = 0; q < 16; q += 4) {
        float4 w, v;
        w = w4[q+0]; v = pn4[q+0]; acc0 += w.x*v.x + w.y*v.y + w.z*v.z + w.w*v.w;
        w = w4[q+1]; v = pn4[q+1]; acc1 += w.x*v.x + w.y*v.y + w.z*v.z + w.w*v.w;
        w = w4[q+2]; v = pn4[q+2]; acc2 += w.x*v.x + w.y*v.y + w.z*v.z + w.w*v.w;
        w = w4[q+3]; v = pn4[q+3]; acc3 += w.x*v.x + w.y*v.y + w.z*v.z + w.w*v.w;
    }
    __shared__ float sh_part[128];
    sh_part[tid] = (acc0 + acc1) + (acc2 + acc3);
    __syncthreads();

    if (tid < 64) {
        const float bias = (tid < 32) ? b1[tid] : b2[tid - 32];
        float val = sh_part[tid] + sh_part[tid + 64] + bias;
        float* dst = (tid < 32) ? g_p1t : g_p2t;
        dst[(b * C + c) * SEQ + s] = val;
    }
}

// ---------------------------------------------------------------------------
// Kernel 3 (fused): per (b,k) block:
//   1) stage p2t[b] (24KB) + Wout row k (4KB) into smem
//   2) build M[c][j] = sum_d p2t[b][d][j] * W[c*32+d]  IN PLACE (col j in regs)
//   3) GEMM: out[i][j] = (sum_c p1t[b][c][i] * M[c][j] + bout[k]) / 2
// 16x16 threads, 12x12 tile per thread; fp32x2 packed FMA along j.
// ---------------------------------------------------------------------------
__global__ __launch_bounds__(256, 1)
void k3_fused(const float* __restrict__ Wout,
              const float* __restrict__ bout,
              float* __restrict__ out) {
    const int bk = blockIdx.x;
    const int b  = bk >> 7;
    const int k  = bk & (C_I - 1);
    const int tid = threadIdx.x;

    __shared__ float S[C][SEQ];       // p2 tile, overwritten by M (24 KB)
    __shared__ float shW[C * C];      // Wout row k (4 KB)

    // stage p2t[b] and W row
    {
        const float4* Pp = (const float4*)(g_p2t + (size_t)b * C * SEQ);
        float4* S4 = (float4*)S;
        #pragma unroll
        for (int t = tid; t < C * SEQ / 4; t += 256) S4[t] = Pp[t];
        ((float4*)shW)[tid] = ((const float4*)(Wout + (size_t)k * C * C))[tid];
    }
    __syncthreads();

    // build M in place: thread j owns column j (j < 192)
    if (tid < SEQ) {
        const int j = tid;
        // q[d] into regs, pack into 16 f32x2 pairs
        unsigned long long qq[16];
        #pragma unroll
        for (int d2 = 0; d2 < 16; ++d2) {
            float qa = S[2 * d2 + 0][j];
            float qb = S[2 * d2 + 1][j];
            PACK_F32X2(qq[d2], qa, qb);
        }
        float m[C];
        #pragma unroll
        for (int c = 0; c < C; ++c) {
            const unsigned long long* w2 = (const unsigned long long*)(shW + c * C);
            unsigned long long acc = 0ull;   // (0.0f, 0.0f)
            #pragma unroll
            for (int d2 = 0; d2 < 16; ++d2)
                FMA_F32X2(acc, qq[d2], w2[d2], acc);
            float lo, hi; UNPACK_F32X2(lo, hi, acc);
            m[c] = lo + hi;
        }
        #pragma unroll
        for (int c = 0; c < C; ++c) S[c][j] = m[c];
    }
    __syncthreads();

    // GEMM: A from global (L1-hot p1t[b]), B = M from smem
    const int tx = tid & 15;
    const int ty = tid >> 4;
    const int i0 = ty * 12;
    const int j0 = tx * 12;
    const float* Ab = g_p1t + (size_t)b * C * SEQ;

    unsigned long long acc[12][6];
    #pragma unroll
    for (int i = 0; i < 12; ++i)
        #pragma unroll
        for (int q = 0; q < 6; ++q) acc[i][q] = 0ull;

    #pragma unroll 4
    for (int kk = 0; kk < C; ++kk) {
        const float* arow = Ab + kk * SEQ + i0;
        float4 a0 = *(const float4*)(arow + 0);
        float4 a1 = *(const float4*)(arow + 4);
        float4 a2 = *(const float4*)(arow + 8);
        float a[12] = { a0.x, a0.y, a0.z, a0.w,
                        a1.x, a1.y, a1.z, a1.w,
                        a2.x, a2.y, a2.z, a2.w };
        const unsigned long long* brow = (const unsigned long long*)&S[kk][j0];
        unsigned long long bp[6];
        #pragma unroll
        for (int q = 0; q < 6; ++q) bp[q] = brow[q];
        #pragma unroll
        for (int i = 0; i < 12; ++i) {
            unsigned long long as;
            PACK_F32X2(as, a[i], a[i]);
            #pragma unroll
            for (int q = 0; q < 6; ++q)
                FMA_F32X2(acc[i][q], as, bp[q], acc[i][q]);
        }
    }

    // epilogue: v = 0.5*acc + 0.5*bias  (packed), then float4 stores
    const float hb = 0.5f * bout[k];
    unsigned long long half2, bias2;
    PACK_F32X2(half2, 0.5f, 0.5f);
    PACK_F32X2(bias2, hb, hb);

    float* obase = out + (size_t)bk * SEQ * SEQ;
    #pragma unroll
    for (int i = 0; i < 12; ++i) {
        float* orow = obase + (size_t)(i0 + i) * SEQ + j0;
        #pragma unroll
        for (int q2 = 0; q2 < 3; ++q2) {
            unsigned long long r0 = acc[i][2 * q2 + 0];
            unsigned long long r1 = acc[i][2 * q2 + 1];
            FMA_F32X2(r0, r0, half2, bias2);
            FMA_F32X2(r1, r1, half2, bias2);
            float4 v;
            UNPACK_F32X2(v.x, v.y, r0);
            UNPACK_F32X2(v.z, v.w, r1);
            *(float4*)(orow + q2 * 4) = v;
        }
    }
}

// ---------------------------------------------------------------------------
extern "C" void kernel_launch(void* const* d_in, const int* in_sizes, int n_in,
                              void* d_out, int out_size) {
    const float* p     = (const float*)d_in[0];
    const float* gamma = (const float*)d_in[1];
    const float* beta  = (const float*)d_in[2];
    const float* W1    = (const float*)d_in[3];
    const float* b1    = (const float*)d_in[4];
    const float* W2    = (const float*)d_in[5];
    const float* b2    = (const float*)d_in[6];
    const float* Wout  = (const float*)d_in[7];
    const float* bout  = (const float*)d_in[8];
    float* out = (float*)d_out;

    k1_ln_proj<<<SEQ * BATCH, C_P>>>(p, gamma, beta, W1, b1, W2, b2);
    k3_fused<<<BATCH * C_I, 256>>>(Wout, bout, out);
}

// round 3
// speedup vs baseline: 1.2520x; 1.1860x over previous
#include <cuda_runtime.h>
#include <cuda_bf16.h>

// Shapes (fixed by the problem)
#define SEQ   192
#define BATCH 2
#define C_P   128
#define C     32
#define C_I   128

// Cross-kernel scratch (device globals: no allocation allowed)
__device__ float g_p1t[BATCH * C * SEQ];          // [b][c][s]
__device__ float g_p2t[BATCH * C * SEQ];          // [b][d][s]

// ---- packed fp32x2 helpers (Blackwell FFMA2) --------------------------------
#define FMA_F32X2(d, a, b, c) \
    asm("fma.rn.f32x2 %0, %1, %2, %3;" : "=l"(d) : "l"(a), "l"(b), "l"(c))
#define PACK_F32X2(out, lo, hi) \
    asm("mov.b64 %0, {%1, %2};" : "=l"(out) : "r"(__float_as_uint(lo)), "r"(__float_as_uint(hi)))
#define UNPACK_F32X2(lo, hi, in) \
    do { unsigned int _l, _h; \
         asm("mov.b64 {%0, %1}, %2;" : "=r"(_l), "=r"(_h) : "l"(in)); \
         lo = __uint_as_float(_l); hi = __uint_as_float(_h); } while (0)

// ---------------------------------------------------------------------------
// Kernel 1: LayerNorm over C_P + dual projections -> transposed p1t/p2t
// ---------------------------------------------------------------------------
__global__ __launch_bounds__(128)
void k1_ln_proj(const float* __restrict__ p,
                const float* __restrict__ gamma,
                const float* __restrict__ beta,
                const float* __restrict__ W1,
                const float* __restrict__ b1,
                const float* __restrict__ W2,
                const float* __restrict__ b2) {
    const int r = blockIdx.x;            // row over (s,b)
    const int s = r / BATCH;
    const int b = r % BATCH;
    const int tid = threadIdx.x;         // 0..127

    float x = p[r * C_P + tid];

    float s1 = x, s2 = x * x;
    #pragma unroll
    for (int off = 16; off > 0; off >>= 1) {
        s1 += __shfl_down_sync(0xFFFFFFFFu, s1, off);
        s2 += __shfl_down_sync(0xFFFFFFFFu, s2, off);
    }
    __shared__ float a1[4], a2[4];
    const int warp = tid >> 5, lane = tid & 31;
    if (lane == 0) { a1[warp] = s1; a2[warp] = s2; }
    __syncthreads();
    float sum  = a1[0] + a1[1] + a1[2] + a1[3];
    float sumq = a2[0] + a2[1] + a2[2] + a2[3];

    const float inv = 1.0f / (float)C_P;
    float mu   = sum * inv;
    float var  = sumq * inv - mu * mu;
    float rstd = rsqrtf(var + 1e-5f);

    __shared__ float sh_pn[C_P];
    sh_pn[tid] = (x - mu) * rstd * gamma[tid] + beta[tid];
    __syncthreads();

    const int  o = tid & 63;
    const int  h = tid >> 6;
    const int  c = (o < 32) ? o : (o - 32);
    const float* W = (o < 32) ? W1 : W2;

    const float4* w4  = (const float4*)(W + c * C_P + h * 64);
    const float4* pn4 = (const float4*)(sh_pn + h * 64);
    float acc0 = 0.f, acc1 = 0.f, acc2 = 0.f, acc3 = 0.f;
    #pragma unroll
    for (int q = 0; q < 16; q += 4) {
        float4 w, v;
        w = w4[q+0]; v = pn4[q+0]; acc0 += w.x*v.x + w.y*v.y + w.z*v.z + w.w*v.w;
        w = w4[q+1]; v = pn4[q+1]; acc1 += w.x*v.x + w.y*v.y + w.z*v.z + w.w*v.w;
        w = w4[q+2]; v = pn4[q+2]; acc2 += w.x*v.x + w.y*v.y + w.z*v.z + w.w*v.w;
        w = w4[q+3]; v = pn4[q+3]; acc3 += w.x*v.x + w.y*v.y + w.z*v.z + w.w*v.w;
    }
    __shared__ float sh_part[128];
    sh_part[tid] = (acc0 + acc1) + (acc2 + acc3);
    __syncthreads();

    if (tid < 64) {
        const float bias = (tid < 32) ? b1[tid] : b2[tid - 32];
        float val = sh_part[tid] + sh_part[tid + 64] + bias;
        float* dst = (tid < 32) ? g_p1t : g_p2t;
        dst[(b * C + c) * SEQ + s] = val;
    }
}

// ---------------------------------------------------------------------------
// Kernel 3 (fused), 512 threads/block, one (b,k) per block:
//   1) stage p2t[b] (24KB) + Wout row k (4KB) into smem
//   2) build M[c][j] in place (384 threads, 2 c-halves per column)
//   3) GEMM 192x192x32: A from L1-hot g_p1t, B=M from smem
//      thread (tx,ty): rows i0=ty*6..+5, cols j = 2*tx + 32*q (q=0..5)
//      fp32x2 packed FMA along j-pairs.
// ---------------------------------------------------------------------------
__global__ __launch_bounds__(512, 1)
void k3_fused(const float* __restrict__ Wout,
              const float* __restrict__ bout,
              float* __restrict__ out) {
    const int bk = blockIdx.x;
    const int b  = bk >> 7;
    const int k  = bk & (C_I - 1);
    const int tid = threadIdx.x;

    __shared__ float S[C][SEQ];       // p2 tile, overwritten by M (24 KB)
    __shared__ float shW[C * C];      // Wout row k (4 KB)

    // stage p2t[b] and W row
    {
        const float4* Pp = (const float4*)(g_p2t + (size_t)b * C * SEQ);
        float4* S4 = (float4*)S;
        #pragma unroll
        for (int t = tid; t < C * SEQ / 4; t += 512) S4[t] = Pp[t];
        if (tid < 256)
            ((float4*)shW)[tid] = ((const float4*)(Wout + (size_t)k * C * C))[tid];
    }
    __syncthreads();

    // ---- build M in place: thread (j, h) computes c in [h*16, h*16+16) ----
    const int j  = tid % SEQ;
    const int hh = tid / SEQ;            // 0,1 active; 2 idle
    unsigned long long qq[16];
    if (hh < 2) {
        #pragma unroll
        for (int d2 = 0; d2 < 16; ++d2) {
            float qa = S[2 * d2 + 0][j];
            float qb = S[2 * d2 + 1][j];
            PACK_F32X2(qq[d2], qa, qb);
        }
    }
    __syncthreads();                     // all reads of S done before writes
    if (hh < 2) {
        float m[16];
        #pragma unroll
        for (int cc = 0; cc < 16; ++cc) {
            const int c = hh * 16 + cc;
            const unsigned long long* w2 = (const unsigned long long*)(shW + c * C);
            unsigned long long acc = 0ull;
            #pragma unroll
            for (int d2 = 0; d2 < 16; ++d2)
                FMA_F32X2(acc, qq[d2], w2[d2], acc);
            float lo, hi; UNPACK_F32X2(lo, hi, acc);
            m[cc] = lo + hi;
        }
        #pragma unroll
        for (int cc = 0; cc < 16; ++cc) S[hh * 16 + cc][j] = m[cc];
    }
    __syncthreads();

    // ---- GEMM ----
    const int tx = tid & 15;             // 16 j-groups
    const int ty = tid >> 4;             // 32 i-groups
    const int i0 = ty * 6;
    const int jb = tx * 2;               // base col; cols jb + 32*q
    const float* Ab = g_p1t + (size_t)b * C * SEQ;

    unsigned long long acc[6][6];
    #pragma unroll
    for (int i = 0; i < 6; ++i)
        #pragma unroll
        for (int q = 0; q < 6; ++q) acc[i][q] = 0ull;

    #pragma unroll 4
    for (int kk = 0; kk < C; ++kk) {
        const float2* arow = (const float2*)(Ab + kk * SEQ + i0);
        float2 a01 = arow[0], a23 = arow[1], a45 = arow[2];
        float a[6] = { a01.x, a01.y, a23.x, a23.y, a45.x, a45.y };

        unsigned long long bp[6];
        #pragma unroll
        for (int q = 0; q < 6; ++q)
            bp[q] = *(const unsigned long long*)&S[kk][jb + 32 * q];

        #pragma unroll
        for (int i = 0; i < 6; ++i) {
            unsigned long long as;
            PACK_F32X2(as, a[i], a[i]);
            #pragma unroll
            for (int q = 0; q < 6; ++q)
                FMA_F32X2(acc[i][q], as, bp[q], acc[i][q]);
        }
    }

    // ---- epilogue: v = 0.5*acc + 0.5*bias (packed), float2 stores ----
    const float hb = 0.5f * bout[k];
    unsigned long long half2, bias2;
    PACK_F32X2(half2, 0.5f, 0.5f);
    PACK_F32X2(bias2, hb, hb);

    float* obase = out + (size_t)bk * SEQ * SEQ;
    #pragma unroll
    for (int i = 0; i < 6; ++i) {
        float* orow = obase + (size_t)(i0 + i) * SEQ;
        #pragma unroll
        for (int q = 0; q < 6; ++q) {
            unsigned long long r = acc[i][q];
            FMA_F32X2(r, r, half2, bias2);
            *(unsigned long long*)(orow + jb + 32 * q) = r;
        }
    }
}

// ---------------------------------------------------------------------------
extern "C" void kernel_launch(void* const* d_in, const int* in_sizes, int n_in,
                              void* d_out, int out_size) {
    const float* p     = (const float*)d_in[0];
    const float* gamma = (const float*)d_in[1];
    const float* beta  = (const float*)d_in[2];
    const float* W1    = (const float*)d_in[3];
    const float* b1    = (const float*)d_in[4];
    const float* W2    = (const float*)d_in[5];
    const float* b2    = (const float*)d_in[6];
    const float* Wout  = (const float*)d_in[7];
    const float* bout  = (const float*)d_in[8];
    float* out = (float*)d_out;

    k1_ln_proj<<<SEQ * BATCH, C_P>>>(p, gamma, beta, W1, b1, W2, b2);
    k3_fused<<<BATCH * C_I, 512>>>(Wout, bout, out);
}

// round 4
// speedup vs baseline: 1.2636x; 1.0092x over previous
#include <cuda_runtime.h>
#include <cstdint>

// Shapes (fixed by the problem)
#define SEQ   192
#define BATCH 2
#define C_P   128
#define C     32
#define C_I   128

// A stride (pad 32 -> 36 so fragment LDS is bank-conflict-free)
#define SA 36
// M stride inside k3 smem (96 cols padded to 104; 104 mod 32 == 8)
#define SM 104

// Cross-kernel scratch
__device__ float g_p1hl[BATCH * 2 * SEQ * SA];   // [b][plane(hi,lo)][s][SA]
__device__ float g_p2t [BATCH * C * SEQ];        // [b][d][s]

// ---- packed fp32x2 helpers (for the M build) -------------------------------
#define FMA_F32X2(d, a, b, c) \
    asm("fma.rn.f32x2 %0, %1, %2, %3;" : "=l"(d) : "l"(a), "l"(b), "l"(c))
#define PACK_F32X2(out, lo, hi) \
    asm("mov.b64 %0, {%1, %2};" : "=l"(out) : "r"(__float_as_uint(lo)), "r"(__float_as_uint(hi)))
#define UNPACK_F32X2(lo, hi, in) \
    do { unsigned int _l, _h; \
         asm("mov.b64 {%0, %1}, %2;" : "=r"(_l), "=r"(_h) : "l"(in)); \
         lo = __uint_as_float(_l); hi = __uint_as_float(_h); } while (0)

// ---- tf32 helpers -----------------------------------------------------------
__device__ __forceinline__ float tf32_rne(float x) {
    uint32_t u;
    asm("cvt.rna.tf32.f32 %0, %1;" : "=r"(u) : "f"(x));
    return __uint_as_float(u);
}

// D += A(tf32) * B(tf32), m16n8k8, fp32 accumulate
#define MMA_TF32(d, a, b) \
    asm volatile("mma.sync.aligned.m16n8k8.row.col.f32.tf32.tf32.f32 " \
        "{%0,%1,%2,%3}, {%4,%5,%6,%7}, {%8,%9}, {%0,%1,%2,%3};" \
        : "+f"((d)[0]), "+f"((d)[1]), "+f"((d)[2]), "+f"((d)[3]) \
        : "r"((a)[0]), "r"((a)[1]), "r"((a)[2]), "r"((a)[3]), \
          "r"((b)[0]), "r"((b)[1]))

// ---------------------------------------------------------------------------
// Kernel 1: LayerNorm + dual projections.
//   p1 -> tf32 hi/lo planes g_p1hl[b][pl][s][SA]   (A of the big GEMM)
//   p2 -> g_p2t[b][d][s]                            (input of the M build)
// ---------------------------------------------------------------------------
__global__ __launch_bounds__(128)
void k1_ln_proj(const float* __restrict__ p,
                const float* __restrict__ gamma,
                const float* __restrict__ beta,
                const float* __restrict__ W1,
                const float* __restrict__ b1,
                const float* __restrict__ W2,
                const float* __restrict__ b2) {
    const int r = blockIdx.x;
    const int s = r / BATCH;
    const int b = r % BATCH;
    const int tid = threadIdx.x;

    float x = p[r * C_P + tid];

    float s1 = x, s2 = x * x;
    #pragma unroll
    for (int off = 16; off > 0; off >>= 1) {
        s1 += __shfl_down_sync(0xFFFFFFFFu, s1, off);
        s2 += __shfl_down_sync(0xFFFFFFFFu, s2, off);
    }
    __shared__ float a1[4], a2[4];
    const int warp = tid >> 5, lane = tid & 31;
    if (lane == 0) { a1[warp] = s1; a2[warp] = s2; }
    __syncthreads();
    float sum  = a1[0] + a1[1] + a1[2] + a1[3];
    float sumq = a2[0] + a2[1] + a2[2] + a2[3];

    const float inv = 1.0f / (float)C_P;
    float mu   = sum * inv;
    float var  = sumq * inv - mu * mu;
    float rstd = rsqrtf(var + 1e-5f);

    __shared__ float sh_pn[C_P];
    sh_pn[tid] = (x - mu) * rstd * gamma[tid] + beta[tid];
    __syncthreads();

    const int  o = tid & 63;
    const int  h = tid >> 6;
    const int  c = (o < 32) ? o : (o - 32);
    const float* W = (o < 32) ? W1 : W2;

    const float4* w4  = (const float4*)(W + c * C_P + h * 64);
    const float4* pn4 = (const float4*)(sh_pn + h * 64);
    float acc0 = 0.f, acc1 = 0.f, acc2 = 0.f, acc3 = 0.f;
    #pragma unroll
    for (int q = 0; q < 16; q += 4) {
        float4 w, v;
        w = w4[q+0]; v = pn4[q+0]; acc0 += w.x*v.x + w.y*v.y + w.z*v.z + w.w*v.w;
        w = w4[q+1]; v = pn4[q+1]; acc1 += w.x*v.x + w.y*v.y + w.z*v.z + w.w*v.w;
        w = w4[q+2]; v = pn4[q+2]; acc2 += w.x*v.x + w.y*v.y + w.z*v.z + w.w*v.w;
        w = w4[q+3]; v = pn4[q+3]; acc3 += w.x*v.x + w.y*v.y + w.z*v.z + w.w*v.w;
    }
    __shared__ float sh_part[128];
    sh_part[tid] = (acc0 + acc1) + (acc2 + acc3);
    __syncthreads();

    if (tid < 64) {
        float val = sh_part[tid] + sh_part[tid + 64];
        if (tid < 32) {               // p1 -> tf32 hi/lo planes
            val += b1[tid];
            float hi = tf32_rne(val);
            float lo = tf32_rne(val - hi);
            g_p1hl[((b * 2 + 0) * SEQ + s) * SA + c] = hi;
            g_p1hl[((b * 2 + 1) * SEQ + s) * SA + c] = lo;
        } else {                      // p2 -> transposed fp32
            val += b2[c];
            g_p2t[(b * C + c) * SEQ + s] = val;
        }
    }
}

// ---------------------------------------------------------------------------
// Kernel 3: per block = (b, k, j-half of 96 cols)
//   1) stage Wout row k (4KB) + A hi/lo planes (54KB) into smem
//   2) build M[c][jloc] (fp32 FFMA2), split into tf32 hi/lo planes (stride SM)
//   3) tensor-core GEMM: 8 warps, each 48(i) x 48(j), m16n8k8 tf32, 3xTF32
// ---------------------------------------------------------------------------
#define SMEM_FLOATS (1024 + 2 * SEQ * SA + 2 * C * SM)   // 1024+13824+6656 = 21504

__global__ __launch_bounds__(256, 2)
void k3_mma(const float* __restrict__ Wout,
            const float* __restrict__ bout,
            float* __restrict__ out) {
    extern __shared__ float sm[];
    float* shW = sm;                        // 1024
    float* sAh = sm + 1024;                 // 192*36
    float* sAl = sAh + SEQ * SA;            // 192*36
    float* sMh = sAl + SEQ * SA;            // 32*104
    float* sMl = sMh + C * SM;              // 32*104

    const int blk = blockIdx.x;
    const int bk  = blk >> 1;
    const int jh  = blk & 1;                // which 96-col half
    const int b   = bk >> 7;
    const int k   = bk & (C_I - 1);
    const int tid = threadIdx.x;

    // ---- stage W row and both A planes (contiguous copy) ----
    ((float4*)shW)[tid] = ((const float4*)(Wout + (size_t)k * C * C))[tid];
    {
        const float4* Ap = (const float4*)(g_p1hl + (size_t)b * 2 * SEQ * SA);
        float4* D = (float4*)sAh;           // sAh,sAl contiguous
        #pragma unroll
        for (int t = tid; t < 2 * SEQ * SA / 4; t += 256) D[t] = Ap[t];
    }
    __syncthreads();

    // ---- build M for this block's 96 columns ----
    {
        const int jloc = tid % 96;
        const int part = tid / 96;          // 0,1 active (each 16 c's)
        if (part < 2) {
            const int j = jh * 96 + jloc;
            const float* P2 = g_p2t + (size_t)b * C * SEQ;
            unsigned long long qq[16];
            #pragma unroll
            for (int d2 = 0; d2 < 16; ++d2) {
                float qa = P2[(2 * d2 + 0) * SEQ + j];
                float qb = P2[(2 * d2 + 1) * SEQ + j];
                PACK_F32X2(qq[d2], qa, qb);
            }
            #pragma unroll
            for (int cc = 0; cc < 16; ++cc) {
                const int c = part * 16 + cc;
                const unsigned long long* w2 = (const unsigned long long*)(shW + c * C);
                unsigned long long acc = 0ull;
                #pragma unroll
                for (int d2 = 0; d2 < 16; ++d2)
                    FMA_F32X2(acc, qq[d2], w2[d2], acc);
                float lo, hi; UNPACK_F32X2(lo, hi, acc);
                float m  = lo + hi;
                float mh = tf32_rne(m);
                float ml = tf32_rne(m - mh);
                sMh[c * SM + jloc] = mh;
                sMl[c * SM + jloc] = ml;
            }
        }
    }
    __syncthreads();

    // ---- tensor-core GEMM ----
    const int wid  = tid >> 5, lane = tid & 31;
    const int wi   = wid >> 1;              // 0..3  -> 48-row band
    const int wj   = wid & 1;               // 0..1  -> 48-col band
    const int g    = lane >> 2;             // group 0..7
    const int t    = lane & 3;              // thread-in-group
    const int ibase = wi * 48;
    const int jbase = wj * 48;

    float acc[3][6][4];
    #pragma unroll
    for (int it = 0; it < 3; ++it)
        #pragma unroll
        for (int jt = 0; jt < 6; ++jt)
            #pragma unroll
            for (int q = 0; q < 4; ++q) acc[it][jt][q] = 0.0f;

    #pragma unroll
    for (int ks = 0; ks < 4; ++ks) {
        // A fragments for the 3 i-tiles (hi and lo planes)
        uint32_t Afh[3][4], Afl[3][4];
        #pragma unroll
        for (int it = 0; it < 3; ++it) {
            const int r0 = (ibase + it * 16 + g) * SA + ks * 8 + t;
            const int r8 = r0 + 8 * SA;
            Afh[it][0] = __float_as_uint(sAh[r0]);
            Afh[it][1] = __float_as_uint(sAh[r8]);
            Afh[it][2] = __float_as_uint(sAh[r0 + 4]);
            Afh[it][3] = __float_as_uint(sAh[r8 + 4]);
            Afl[it][0] = __float_as_uint(sAl[r0]);
            Afl[it][1] = __float_as_uint(sAl[r8]);
            Afl[it][2] = __float_as_uint(sAl[r0 + 4]);
            Afl[it][3] = __float_as_uint(sAl[r8 + 4]);
        }
        #pragma unroll
        for (int jt = 0; jt < 6; ++jt) {
            const int cb = (ks * 8 + t) * SM + jbase + jt * 8 + g;
            uint32_t Bh[2], Bl[2];
            Bh[0] = __float_as_uint(sMh[cb]);
            Bh[1] = __float_as_uint(sMh[cb + 4 * SM]);
            Bl[0] = __float_as_uint(sMl[cb]);
            Bl[1] = __float_as_uint(sMl[cb + 4 * SM]);
            #pragma unroll
            for (int it = 0; it < 3; ++it) {
                MMA_TF32(acc[it][jt], Afh[it], Bh);
                MMA_TF32(acc[it][jt], Afh[it], Bl);
                MMA_TF32(acc[it][jt], Afl[it], Bh);
            }
        }
    }

    // ---- epilogue: (acc + bias) * 0.5, float2 stores ----
    const float bias = bout[k];
    float* ob = out + (size_t)bk * SEQ * SEQ + jh * 96;
    #pragma unroll
    for (int it = 0; it < 3; ++it) {
        const int row = ibase + it * 16 + g;
        #pragma unroll
        for (int jt = 0; jt < 6; ++jt) {
            const int col = jbase + jt * 8 + 2 * t;
            float2 v0, v1;
            v0.x = (acc[it][jt][0] + bias) * 0.5f;
            v0.y = (acc[it][jt][1] + bias) * 0.5f;
            v1.x = (acc[it][jt][2] + bias) * 0.5f;
            v1.y = (acc[it][jt][3] + bias) * 0.5f;
            *(float2*)(ob + (size_t)row * SEQ + col)       = v0;
            *(float2*)(ob + (size_t)(row + 8) * SEQ + col) = v1;
        }
    }
}

// ---------------------------------------------------------------------------
extern "C" void kernel_launch(void* const* d_in, const int* in_sizes, int n_in,
                              void* d_out, int out_size) {
    const float* p     = (const float*)d_in[0];
    const float* gamma = (const float*)d_in[1];
    const float* beta  = (const float*)d_in[2];
    const float* W1    = (const float*)d_in[3];
    const float* b1    = (const float*)d_in[4];
    const float* W2    = (const float*)d_in[5];
    const float* b2    = (const float*)d_in[6];
    const float* Wout  = (const float*)d_in[7];
    const float* bout  = (const float*)d_in[8];
    float* out = (float*)d_out;

    cudaFuncSetAttribute(k3_mma, cudaFuncAttributeMaxDynamicSharedMemorySize,
                         SMEM_FLOATS * sizeof(float));

    k1_ln_proj<<<SEQ * BATCH, C_P>>>(p, gamma, beta, W1, b1, W2, b2);
    k3_mma<<<BATCH * C_I * 2, 256, SMEM_FLOATS * sizeof(float)>>>(Wout, bout, out);
}

// round 5
// speedup vs baseline: 1.4409x; 1.1404x over previous
#include <cuda_runtime.h>
#include <cuda_bf16.h>
#include <cstdint>

// Shapes (fixed by the problem)
#define SEQ   192
#define BATCH 2
#define C_P   128
#define C     32
#define C_I   128

// ---------------------------------------------------------------------------
// Global scratch (device globals: no allocation allowed)
// A fragments: [b][plane][ks(2)][itile(12)][lane(32)][reg(4)] as bf16x2 words
__device__ uint32_t g_p1f[BATCH * 2 * 2 * 12 * 32 * 4];      // 49 KB
// B (=M) fragments: [bk(256)][plane][ks(2)][jtile(24)][lane(32)][reg(2)]
__device__ uint32_t g_Mf[BATCH * C_I * 2 * 3072];            // 6.29 MB
// p2 transposed fp32: [b][d][s]
__device__ float    g_p2t[BATCH * C * SEQ];

// ---- packed fp32x2 helpers (FFMA2, for M build) -----------------------------
#define FMA_F32X2(d, a, b, c) \
    asm("fma.rn.f32x2 %0, %1, %2, %3;" : "=l"(d) : "l"(a), "l"(b), "l"(c))
#define PACK_F32X2(out, lo, hi) \
    asm("mov.b64 %0, {%1, %2};" : "=l"(out) : "r"(__float_as_uint(lo)), "r"(__float_as_uint(hi)))
#define UNPACK_F32X2(lo, hi, in) \
    do { unsigned int _l, _h; \
         asm("mov.b64 {%0, %1}, %2;" : "=r"(_l), "=r"(_h) : "l"(in)); \
         lo = __uint_as_float(_l); hi = __uint_as_float(_h); } while (0)

// bf16 mma: D += A * B,  m16n8k16, fp32 accumulate
#define MMA_BF16(d, a, b) \
    asm volatile("mma.sync.aligned.m16n8k16.row.col.f32.bf16.bf16.f32 " \
        "{%0,%1,%2,%3}, {%4,%5,%6,%7}, {%8,%9}, {%0,%1,%2,%3};" \
        : "+f"((d)[0]), "+f"((d)[1]), "+f"((d)[2]), "+f"((d)[3]) \
        : "r"((a).x), "r"((a).y), "r"((a).z), "r"((a).w), \
          "r"((b).x), "r"((b).y))

__device__ __forceinline__ void bf16_split(float v, uint32_t& h, uint32_t& l) {
    __nv_bfloat16 hb = __float2bfloat16(v);
    float hf = __bfloat162float(hb);
    __nv_bfloat16 lb = __float2bfloat16(v - hf);
    h = (uint32_t)__bfloat16_as_ushort(hb);
    l = (uint32_t)__bfloat16_as_ushort(lb);
}

// ---------------------------------------------------------------------------
// Kernel 1: LayerNorm + dual projections.
//   p1 -> bf16 hi/lo A-fragments (g_p1f), p2 -> fp32 transposed (g_p2t)
// ---------------------------------------------------------------------------
__global__ __launch_bounds__(128)
void k1_ln_proj(const float* __restrict__ p,
                const float* __restrict__ gamma,
                const float* __restrict__ beta,
                const float* __restrict__ W1,
                const float* __restrict__ b1,
                const float* __restrict__ W2,
                const float* __restrict__ b2) {
    const int r = blockIdx.x;
    const int s = r / BATCH;
    const int b = r % BATCH;
    const int tid = threadIdx.x;

    float x = p[r * C_P + tid];

    float s1 = x, s2 = x * x;
    #pragma unroll
    for (int off = 16; off > 0; off >>= 1) {
        s1 += __shfl_down_sync(0xFFFFFFFFu, s1, off);
        s2 += __shfl_down_sync(0xFFFFFFFFu, s2, off);
    }
    __shared__ float a1[4], a2[4];
    const int warp = tid >> 5, lane = tid & 31;
    if (lane == 0) { a1[warp] = s1; a2[warp] = s2; }
    __syncthreads();
    float sum  = a1[0] + a1[1] + a1[2] + a1[3];
    float sumq = a2[0] + a2[1] + a2[2] + a2[3];

    const float inv = 1.0f / (float)C_P;
    float mu   = sum * inv;
    float var  = sumq * inv - mu * mu;
    float rstd = rsqrtf(var + 1e-5f);

    __shared__ float sh_pn[C_P];
    sh_pn[tid] = (x - mu) * rstd * gamma[tid] + beta[tid];
    __syncthreads();

    const int  o = tid & 63;
    const int  h = tid >> 6;
    const int  c = (o < 32) ? o : (o - 32);
    const float* W = (o < 32) ? W1 : W2;

    const float4* w4  = (const float4*)(W + c * C_P + h * 64);
    const float4* pn4 = (const float4*)(sh_pn + h * 64);
    float acc0 = 0.f, acc1 = 0.f, acc2 = 0.f, acc3 = 0.f;
    #pragma unroll
    for (int q = 0; q < 16; q += 4) {
        float4 w, v;
        w = w4[q+0]; v = pn4[q+0]; acc0 += w.x*v.x + w.y*v.y + w.z*v.z + w.w*v.w;
        w = w4[q+1]; v = pn4[q+1]; acc1 += w.x*v.x + w.y*v.y + w.z*v.z + w.w*v.w;
        w = w4[q+2]; v = pn4[q+2]; acc2 += w.x*v.x + w.y*v.y + w.z*v.z + w.w*v.w;
        w = w4[q+3]; v = pn4[q+3]; acc3 += w.x*v.x + w.y*v.y + w.z*v.z + w.w*v.w;
    }
    __shared__ float sh_part[128];
    sh_part[tid] = (acc0 + acc1) + (acc2 + acc3);
    __syncthreads();

    if (tid < 64) {
        float val = sh_part[tid] + sh_part[tid + 64];
        if (tid < 32) {
            // p1 -> A fragments (bf16 hi/lo)
            val += b1[tid];
            uint32_t hu, lu;
            bf16_split(val, hu, lu);
            uint32_t hu1 = __shfl_down_sync(0xFFFFFFFFu, hu, 1);
            uint32_t lu1 = __shfl_down_sync(0xFFFFFFFFu, lu, 1);
            if ((tid & 1) == 0) {
                const int cch  = tid;        // even channel
                const int it   = s >> 4;
                const int grow = s & 15;
                const int g    = grow & 7;
                const int top  = grow >> 3;
                const int ks   = cch >> 4;
                const int cl   = cch & 15;
                const int rhi  = cl >> 3;
                const int t    = (cl & 7) >> 1;
                const int reg  = top + 2 * rhi;
                const int ln   = g * 4 + t;
                const int i0 = ((((b * 2 + 0) * 2 + ks) * 12 + it) * 32 + ln) * 4 + reg;
                const int i1 = ((((b * 2 + 1) * 2 + ks) * 12 + it) * 32 + ln) * 4 + reg;
                g_p1f[i0] = hu | (hu1 << 16);
                g_p1f[i1] = lu | (lu1 << 16);
            }
        } else {
            val += b2[tid - 32];
            g_p2t[(b * C + (tid - 32)) * SEQ + s] = val;
        }
    }
}

// ---------------------------------------------------------------------------
// Kernel 2: per (b,k): M[c][j] = sum_d p2t[b][d][j] * Wout[k][c*32+d],
// then split to bf16 hi/lo and repack into MMA B-fragment order in g_Mf.
// 384 threads: j = tid%192, c-half = tid/192.
// ---------------------------------------------------------------------------
#define SMP 193   // sM row stride (odd -> conflict-light)

__global__ __launch_bounds__(384)
void k2_build_M(const float* __restrict__ Wout) {
    const int bk = blockIdx.x;
    const int b  = bk >> 7;
    const int k  = bk & (C_I - 1);
    const int tid = threadIdx.x;

    __shared__ float shW[C * C];          // 4 KB
    __shared__ float sM[C][SMP];          // 24.7 KB

    if (tid < 256)
        ((float4*)shW)[tid] = ((const float4*)(Wout + (size_t)k * C * C))[tid];
    __syncthreads();

    // build M: thread (j, half) computes c in [half*16, half*16+16)
    {
        const int j    = tid % SEQ;
        const int half = tid / SEQ;       // 0 or 1
        const float* P2 = g_p2t + (size_t)b * C * SEQ;
        unsigned long long qq[16];
        #pragma unroll
        for (int d2 = 0; d2 < 16; ++d2) {
            float qa = P2[(2 * d2 + 0) * SEQ + j];
            float qb = P2[(2 * d2 + 1) * SEQ + j];
            PACK_F32X2(qq[d2], qa, qb);
        }
        #pragma unroll
        for (int cc = 0; cc < 16; ++cc) {
            const int c = half * 16 + cc;
            const unsigned long long* w2 = (const unsigned long long*)(shW + c * C);
            unsigned long long acc = 0ull;
            #pragma unroll
            for (int d2 = 0; d2 < 16; ++d2)
                FMA_F32X2(acc, qq[d2], w2[d2], acc);
            float lo, hi; UNPACK_F32X2(lo, hi, acc);
            sM[c][j] = lo + hi;
        }
    }
    __syncthreads();

    // repack to fragment order: u = ((ks*24 + jt)*32 + lane)*2 + reg
    uint32_t* dst = g_Mf + (size_t)bk * 2 * 3072;
    #pragma unroll
    for (int u = tid; u < 3072; u += 384) {
        const int reg  = u & 1;
        const int ln   = (u >> 1) & 31;
        const int rest = u >> 6;           // ks*24 + jt
        const int jt   = rest % 24;
        const int ks   = rest / 24;
        const int g    = ln >> 2, t = ln & 3;
        const int j2   = jt * 8 + g;
        const int c0   = ks * 16 + reg * 8 + 2 * t;
        float m0 = sM[c0][j2];
        float m1 = sM[c0 + 1][j2];
        uint32_t h0, l0, h1, l1;
        bf16_split(m0, h0, l0);
        bf16_split(m1, h1, l1);
        dst[u]        = h0 | (h1 << 16);
        dst[3072 + u] = l0 | (l1 << 16);
    }
}

// ---------------------------------------------------------------------------
// Kernel 3: pure-register tensor-core GEMM. No smem, no syncs.
// grid = 256 bk * 3 j-thirds; 256 threads; warp tile 48(i) x 32(j).
// 3-term bf16: hi*hi + hi*lo + lo*hi, fp32 accumulate.
// ---------------------------------------------------------------------------
__global__ __launch_bounds__(256, 2)
void k3_mma(const float* __restrict__ bout, float* __restrict__ out) {
    const int blk    = blockIdx.x;
    const int bk     = blk / 3;
    const int jthird = blk % 3;
    const int b      = bk >> 7;
    const int k      = bk & (C_I - 1);
    const int tid    = threadIdx.x;
    const int wid    = tid >> 5, lane = tid & 31;
    const int wi     = wid >> 1;                 // 0..3 i-band (48 rows)
    const int wj     = wid & 1;                  // 0..1 j-band (32 cols)
    const int jtbase = jthird * 8 + wj * 4;      // first 8-col tile

    float acc[3][4][4];
    #pragma unroll
    for (int i = 0; i < 3; ++i)
        #pragma unroll
        for (int j = 0; j < 4; ++j)
            #pragma unroll
            for (int q = 0; q < 4; ++q) acc[i][j][q] = 0.0f;

    const uint4*    Af = (const uint4*)g_p1f;    // [b][pl][ks][it][lane] -> uint4
    const uint32_t* Mf = g_Mf + (size_t)bk * 2 * 3072;

    #pragma unroll
    for (int ks = 0; ks < 2; ++ks) {
        uint4 Ah[3], Al[3];
        #pragma unroll
        for (int itl = 0; itl < 3; ++itl) {
            const int it = wi * 3 + itl;
            Ah[itl] = Af[(((b * 2 + 0) * 2 + ks) * 12 + it) * 32 + lane];
            Al[itl] = Af[(((b * 2 + 1) * 2 + ks) * 12 + it) * 32 + lane];
        }
        uint2 Bh[4], Bl[4];
        #pragma unroll
        for (int jtl = 0; jtl < 4; ++jtl) {
            const int jt = jtbase + jtl;
            const int o  = ((ks * 24 + jt) * 32 + lane) * 2;
            Bh[jtl] = *(const uint2*)(Mf + o);
            Bl[jtl] = *(const uint2*)(Mf + 3072 + o);
        }
        #pragma unroll
        for (int itl = 0; itl < 3; ++itl)
            #pragma unroll
            for (int jtl = 0; jtl < 4; ++jtl) {
                MMA_BF16(acc[itl][jtl], Ah[itl], Bh[jtl]);
                MMA_BF16(acc[itl][jtl], Ah[itl], Bl[jtl]);
                MMA_BF16(acc[itl][jtl], Al[itl], Bh[jtl]);
            }
    }

    // epilogue: (acc + bias) * 0.5
    const float bias = bout[k];
    const int g = lane >> 2, t = lane & 3;
    float* ob = out + (size_t)bk * SEQ * SEQ;
    #pragma unroll
    for (int itl = 0; itl < 3; ++itl) {
        const int row = (wi * 3 + itl) * 16 + g;
        #pragma unroll
        for (int jtl = 0; jtl < 4; ++jtl) {
            const int col = (jtbase + jtl) * 8 + 2 * t;
            float2 v0, v1;
            v0.x = (acc[itl][jtl][0] + bias) * 0.5f;
            v0.y = (acc[itl][jtl][1] + bias) * 0.5f;
            v1.x = (acc[itl][jtl][2] + bias) * 0.5f;
            v1.y = (acc[itl][jtl][3] + bias) * 0.5f;
            *(float2*)(ob + (size_t)row * SEQ + col)       = v0;
            *(float2*)(ob + (size_t)(row + 8) * SEQ + col) = v1;
        }
    }
}

// ---------------------------------------------------------------------------
extern "C" void kernel_launch(void* const* d_in, const int* in_sizes, int n_in,
                              void* d_out, int out_size) {
    const float* p     = (const float*)d_in[0];
    const float* gamma = (const float*)d_in[1];
    const float* beta  = (const float*)d_in[2];
    const float* W1    = (const float*)d_in[3];
    const float* b1    = (const float*)d_in[4];
    const float* W2    = (const float*)d_in[5];
    const float* b2    = (const float*)d_in[6];
    const float* Wout  = (const float*)d_in[7];
    const float* bout  = (const float*)d_in[8];
    float* out = (float*)d_out;

    k1_ln_proj<<<SEQ * BATCH, C_P>>>(p, gamma, beta, W1, b1, W2, b2);
    k2_build_M<<<BATCH * C_I, 384>>>(Wout);
    k3_mma<<<BATCH * C_I * 3, 256>>>(bout, out);
}

// round 6
// speedup vs baseline: 1.4790x; 1.0264x over previous
#include <cuda_runtime.h>
#include <cuda_bf16.h>
#include <cstdint>

// Shapes (fixed by the problem)
#define SEQ   192
#define BATCH 2
#define C_P   128
#define C     32
#define C_I   128

// ---------------------------------------------------------------------------
// Global scratch
// A fragments: [b][plane][ks(2)][itile(12)][lane(32)][reg(4)] as bf16x2 words
__device__ uint32_t g_p1f[BATCH * 2 * 2 * 12 * 32 * 4];      // 49 KB
// p2 transposed fp32: [b][d][s]
__device__ float    g_p2t[BATCH * C * SEQ];

// ---- packed fp32x2 helpers (FFMA2, for M build) -----------------------------
#define FMA_F32X2(d, a, b, c) \
    asm("fma.rn.f32x2 %0, %1, %2, %3;" : "=l"(d) : "l"(a), "l"(b), "l"(c))
#define PACK_F32X2(out, lo, hi) \
    asm("mov.b64 %0, {%1, %2};" : "=l"(out) : "r"(__float_as_uint(lo)), "r"(__float_as_uint(hi)))
#define UNPACK_F32X2(lo, hi, in) \
    do { unsigned int _l, _h; \
         asm("mov.b64 {%0, %1}, %2;" : "=r"(_l), "=r"(_h) : "l"(in)); \
         lo = __uint_as_float(_l); hi = __uint_as_float(_h); } while (0)

// bf16 mma: D += A * B,  m16n8k16, fp32 accumulate
#define MMA_BF16(d, a, b) \
    asm volatile("mma.sync.aligned.m16n8k16.row.col.f32.bf16.bf16.f32 " \
        "{%0,%1,%2,%3}, {%4,%5,%6,%7}, {%8,%9}, {%0,%1,%2,%3};" \
        : "+f"((d)[0]), "+f"((d)[1]), "+f"((d)[2]), "+f"((d)[3]) \
        : "r"((a).x), "r"((a).y), "r"((a).z), "r"((a).w), \
          "r"((b).x), "r"((b).y))

__device__ __forceinline__ void bf16_split(float v, uint32_t& h, uint32_t& l) {
    __nv_bfloat16 hb = __float2bfloat16(v);
    float hf = __bfloat162float(hb);
    __nv_bfloat16 lb = __float2bfloat16(v - hf);
    h = (uint32_t)__bfloat16_as_ushort(hb);
    l = (uint32_t)__bfloat16_as_ushort(lb);
}

// ---------------------------------------------------------------------------
// Kernel 1: LayerNorm + dual projections. 256 threads/block, 1 row/block.
//   Projection split (64 outputs x 4 channel-quarters) for a short chain.
//   p1 -> bf16 hi/lo A-fragments (g_p1f), p2 -> fp32 transposed (g_p2t)
// ---------------------------------------------------------------------------
__global__ __launch_bounds__(256)
void k1_ln_proj(const float* __restrict__ p,
                const float* __restrict__ gamma,
                const float* __restrict__ beta,
                const float* __restrict__ W1,
                const float* __restrict__ b1,
                const float* __restrict__ W2,
                const float* __restrict__ b2) {
    const int r = blockIdx.x;
    const int s = r / BATCH;
    const int b = r % BATCH;
    const int tid = threadIdx.x;

    __shared__ float a1[4], a2[4];
    __shared__ float sh_pn[C_P];
    __shared__ float sh_part[256];

    // ---- LayerNorm stats (threads 0..127) ----
    if (tid < C_P) {
        float x = p[r * C_P + tid];
        float s1 = x, s2 = x * x;
        #pragma unroll
        for (int off = 16; off > 0; off >>= 1) {
            s1 += __shfl_down_sync(0xFFFFFFFFu, s1, off);
            s2 += __shfl_down_sync(0xFFFFFFFFu, s2, off);
        }
        const int warp = tid >> 5, lane = tid & 31;
        if (lane == 0) { a1[warp] = s1; a2[warp] = s2; }
        // stash x for after the sync via sh_pn temporarily
        sh_pn[tid] = x;
    }
    __syncthreads();
    {
        float sum  = a1[0] + a1[1] + a1[2] + a1[3];
        float sumq = a2[0] + a2[1] + a2[2] + a2[3];
        const float inv = 1.0f / (float)C_P;
        float mu   = sum * inv;
        float var  = sumq * inv - mu * mu;
        float rstd = rsqrtf(var + 1e-5f);
        if (tid < C_P) {
            float x = sh_pn[tid];
            // overwrite with normalized value next sync
            sh_part[tid] = (x - mu) * rstd * gamma[tid] + beta[tid];
        }
    }
    __syncthreads();
    if (tid < C_P) sh_pn[tid] = sh_part[tid];
    __syncthreads();

    // ---- projection: o = tid&63, quarter q = tid>>6 (32 channels each) ----
    const int  o = tid & 63;
    const int  q = tid >> 6;
    const int  c = (o < 32) ? o : (o - 32);
    const float* W = (o < 32) ? W1 : W2;

    const float4* w4  = (const float4*)(W + c * C_P + q * 32);
    const float4* pn4 = (const float4*)(sh_pn + q * 32);
    float acc0 = 0.f, acc1 = 0.f;
    #pragma unroll
    for (int u = 0; u < 8; u += 2) {
        float4 w, v;
        w = w4[u+0]; v = pn4[u+0]; acc0 += w.x*v.x + w.y*v.y + w.z*v.z + w.w*v.w;
        w = w4[u+1]; v = pn4[u+1]; acc1 += w.x*v.x + w.y*v.y + w.z*v.z + w.w*v.w;
    }
    sh_part[tid] = acc0 + acc1;
    __syncthreads();

    if (tid < 64) {
        float val = sh_part[tid] + sh_part[tid + 64]
                  + sh_part[tid + 128] + sh_part[tid + 192];
        if (tid < 32) {
            // p1 -> A fragments (bf16 hi/lo), pair even/odd channels via shfl
            val += b1[tid];
            uint32_t hu, lu;
            bf16_split(val, hu, lu);
            uint32_t hu1 = __shfl_down_sync(0xFFFFFFFFu, hu, 1);
            uint32_t lu1 = __shfl_down_sync(0xFFFFFFFFu, lu, 1);
            if ((tid & 1) == 0) {
                const int cch  = tid;
                const int it   = s >> 4;
                const int grow = s & 15;
                const int g    = grow & 7;
                const int top  = grow >> 3;
                const int ks   = cch >> 4;
                const int cl   = cch & 15;
                const int rhi  = cl >> 3;
                const int t    = (cl & 7) >> 1;
                const int reg  = top + 2 * rhi;
                const int ln   = g * 4 + t;
                const int i0 = ((((b * 2 + 0) * 2 + ks) * 12 + it) * 32 + ln) * 4 + reg;
                const int i1 = ((((b * 2 + 1) * 2 + ks) * 12 + it) * 32 + ln) * 4 + reg;
                g_p1f[i0] = hu | (hu1 << 16);
                g_p1f[i1] = lu | (lu1 << 16);
            }
        } else {
            val += b2[tid - 32];
            g_p2t[(b * C + (tid - 32)) * SEQ + s] = val;
        }
    }
}

// ---------------------------------------------------------------------------
// Kernel 3 (fused M-build + MMA). grid = 512 (bk x j-half), 256 threads.
//   1) stage Wout row k (4 KB)
//   2) build M for this block's 96 cols (FFMA2), bf16-split, write fragment-
//      ordered B directly to smem: sB[plane][ks][jt(12)][lane(32)][reg(2)]
//   3) MMA: 8 warps = 4 i-bands (48 rows) x 2 j-bands (48 cols); 3-term bf16.
// ---------------------------------------------------------------------------
__global__ __launch_bounds__(256, 2)
void k3_fused(const float* __restrict__ Wout,
              const float* __restrict__ bout,
              float* __restrict__ out) {
    const int blk = blockIdx.x;
    const int bk  = blk >> 1;
    const int jh  = blk & 1;
    const int b   = bk >> 7;
    const int k   = bk & (C_I - 1);
    const int tid = threadIdx.x;

    __shared__ float    shW[C * C];                 // 4 KB
    __shared__ uint32_t sB[2 * 2 * 12 * 32 * 2];    // 12 KB fragments

    ((float4*)shW)[tid] = ((const float4*)(Wout + (size_t)k * C * C))[tid];
    __syncthreads();

    // ---- M build: threads 0..191 -> (jloc = tid%96, ks = tid/96) ----
    if (tid < 192) {
        const int jloc = tid % 96;
        const int ks   = tid / 96;                  // c-half == MMA ks step
        const int j    = jh * 96 + jloc;
        const float* P2 = g_p2t + (size_t)b * C * SEQ;

        unsigned long long qq[16];
        #pragma unroll
        for (int d2 = 0; d2 < 16; ++d2) {
            float qa = P2[(2 * d2 + 0) * SEQ + j];
            float qb = P2[(2 * d2 + 1) * SEQ + j];
            PACK_F32X2(qq[d2], qa, qb);
        }
        float m[16];
        #pragma unroll
        for (int cc = 0; cc < 16; ++cc) {
            const int c = ks * 16 + cc;
            const unsigned long long* w2 = (const unsigned long long*)(shW + c * C);
            unsigned long long acc = 0ull;
            #pragma unroll
            for (int d2 = 0; d2 < 16; ++d2)
                FMA_F32X2(acc, qq[d2], w2[d2], acc);
            float lo, hi; UNPACK_F32X2(lo, hi, acc);
            m[cc] = lo + hi;
        }
        // write fragments: jt = jloc/8, g = jloc%8; lane = g*4+t
        const int jt = jloc >> 3;
        const int g  = jloc & 7;
        #pragma unroll
        for (int reg = 0; reg < 2; ++reg)
            #pragma unroll
            for (int t = 0; t < 4; ++t) {
                const int c0 = reg * 8 + 2 * t;
                uint32_t h0, l0, h1, l1;
                bf16_split(m[c0],     h0, l0);
                bf16_split(m[c0 + 1], h1, l1);
                const int lane = g * 4 + t;
                sB[((0 * 2 + ks) * 12 + jt) * 64 + lane * 2 + reg] = h0 | (h1 << 16);
                sB[((1 * 2 + ks) * 12 + jt) * 64 + lane * 2 + reg] = l0 | (l1 << 16);
            }
    }
    __syncthreads();

    // ---- MMA ----
    const int wid  = tid >> 5, lane = tid & 31;
    const int wi   = wid >> 1;                      // 0..3
    const int wj   = wid & 1;                       // 0..1

    float acc[3][6][4];
    #pragma unroll
    for (int i = 0; i < 3; ++i)
        #pragma unroll
        for (int j = 0; j < 6; ++j)
            #pragma unroll
            for (int qq = 0; qq < 4; ++qq) acc[i][j][qq] = 0.0f;

    const uint4* Af = (const uint4*)g_p1f;

    #pragma unroll
    for (int ks = 0; ks < 2; ++ks) {
        uint4 Ah[3], Al[3];
        #pragma unroll
        for (int itl = 0; itl < 3; ++itl) {
            const int it = wi * 3 + itl;
            Ah[itl] = Af[(((b * 2 + 0) * 2 + ks) * 12 + it) * 32 + lane];
            Al[itl] = Af[(((b * 2 + 1) * 2 + ks) * 12 + it) * 32 + lane];
        }
        #pragma unroll
        for (int jtl = 0; jtl < 6; ++jtl) {
            const int jt = wj * 6 + jtl;
            uint2 Bh = *(const uint2*)&sB[((0 * 2 + ks) * 12 + jt) * 64 + lane * 2];
            uint2 Bl = *(const uint2*)&sB[((1 * 2 + ks) * 12 + jt) * 64 + lane * 2];
            #pragma unroll
            for (int itl = 0; itl < 3; ++itl) {
                MMA_BF16(acc[itl][jtl], Ah[itl], Bh);
                MMA_BF16(acc[itl][jtl], Ah[itl], Bl);
                MMA_BF16(acc[itl][jtl], Al[itl], Bh);
            }
        }
    }

    // ---- epilogue: (acc + bias) * 0.5 ----
    const float bias = bout[k];
    const int g = lane >> 2, t = lane & 3;
    float* ob = out + (size_t)bk * SEQ * SEQ + jh * 96;
    #pragma unroll
    for (int itl = 0; itl < 3; ++itl) {
        const int row = (wi * 3 + itl) * 16 + g;
        #pragma unroll
        for (int jtl = 0; jtl < 6; ++jtl) {
            const int col = (wj * 6 + jtl) * 8 + 2 * t;
            float2 v0, v1;
            v0.x = (acc[itl][jtl][0] + bias) * 0.5f;
            v0.y = (acc[itl][jtl][1] + bias) * 0.5f;
            v1.x = (acc[itl][jtl][2] + bias) * 0.5f;
            v1.y = (acc[itl][jtl][3] + bias) * 0.5f;
            *(float2*)(ob + (size_t)row * SEQ + col)       = v0;
            *(float2*)(ob + (size_t)(row + 8) * SEQ + col) = v1;
        }
    }
}

// ---------------------------------------------------------------------------
extern "C" void kernel_launch(void* const* d_in, const int* in_sizes, int n_in,
                              void* d_out, int out_size) {
    const float* p     = (const float*)d_in[0];
    const float* gamma = (const float*)d_in[1];
    const float* beta  = (const float*)d_in[2];
    const float* W1    = (const float*)d_in[3];
    const float* b1    = (const float*)d_in[4];
    const float* W2    = (const float*)d_in[5];
    const float* b2    = (const float*)d_in[6];
    const float* Wout  = (const float*)d_in[7];
    const float* bout  = (const float*)d_in[8];
    float* out = (float*)d_out;

    k1_ln_proj<<<SEQ * BATCH, 256>>>(p, gamma, beta, W1, b1, W2, b2);
    k3_fused<<<BATCH * C_I * 2, 256>>>(Wout, bout, out);
}

// round 7
// speedup vs baseline: 1.7135x; 1.1586x over previous
#include <cuda_runtime.h>
#include <cuda_bf16.h>
#include <cstdint>

// Shapes (fixed by the problem)
#define SEQ   192
#define BATCH 2
#define C_P   128
#define C     32
#define C_I   128

// ---------------------------------------------------------------------------
// Global scratch
// A fragments: [b][plane][ks(2)][itile(12)][lane(32)][reg(4)] as bf16x2 words
__device__ uint32_t g_p1f[BATCH * 2 * 2 * 12 * 32 * 4];      // 49 KB
// p2 transposed fp32: [b][d][s]
__device__ float    g_p2t[BATCH * C * SEQ];

// ---- packed fp32x2 helpers ---------------------------------------------------
#define FMA_F32X2(d, a, b, c) \
    asm("fma.rn.f32x2 %0, %1, %2, %3;" : "=l"(d) : "l"(a), "l"(b), "l"(c))
#define PACK_F32X2(out, lo, hi) \
    asm("mov.b64 %0, {%1, %2};" : "=l"(out) : "r"(__float_as_uint(lo)), "r"(__float_as_uint(hi)))
#define UNPACK_F32X2(lo, hi, in) \
    do { unsigned int _l, _h; \
         asm("mov.b64 {%0, %1}, %2;" : "=r"(_l), "=r"(_h) : "l"(in)); \
         lo = __uint_as_float(_l); hi = __uint_as_float(_h); } while (0)

// bf16 mma: D += A * B,  m16n8k16, fp32 accumulate
#define MMA_BF16(d, a, b) \
    asm volatile("mma.sync.aligned.m16n8k16.row.col.f32.bf16.bf16.f32 " \
        "{%0,%1,%2,%3}, {%4,%5,%6,%7}, {%8,%9}, {%0,%1,%2,%3};" \
        : "+f"((d)[0]), "+f"((d)[1]), "+f"((d)[2]), "+f"((d)[3]) \
        : "r"((a).x), "r"((a).y), "r"((a).z), "r"((a).w), \
          "r"((b).x), "r"((b).y))

__device__ __forceinline__ void bf16_split(float v, uint32_t& h, uint32_t& l) {
    __nv_bfloat16 hb = __float2bfloat16(v);
    float hf = __bfloat162float(hb);
    __nv_bfloat16 lb = __float2bfloat16(v - hf);
    h = (uint32_t)__bfloat16_as_ushort(hb);
    l = (uint32_t)__bfloat16_as_ushort(lb);
}

// ---------------------------------------------------------------------------
// Kernel 1: LayerNorm + dual projections, coalesced W access.
// 256 threads: o = tid>>2 (0..63 outputs), t = tid&3 (channel quarter, strided)
// ---------------------------------------------------------------------------
__global__ __launch_bounds__(256)
void k1_ln_proj(const float* __restrict__ p,
                const float* __restrict__ gamma,
                const float* __restrict__ beta,
                const float* __restrict__ W1,
                const float* __restrict__ b1,
                const float* __restrict__ W2,
                const float* __restrict__ b2) {
    const int r = blockIdx.x;
    const int s = r / BATCH;
    const int b = r % BATCH;
    const int tid = threadIdx.x;

    __shared__ float a1[4], a2[4];
    __shared__ float sh_pn[C_P];
    __shared__ float sh_res[64];

    // ---- LayerNorm stats (threads 0..127) ----
    if (tid < C_P) {
        float x = p[r * C_P + tid];
        float s1 = x, s2 = x * x;
        #pragma unroll
        for (int off = 16; off > 0; off >>= 1) {
            s1 += __shfl_down_sync(0xFFFFFFFFu, s1, off);
            s2 += __shfl_down_sync(0xFFFFFFFFu, s2, off);
        }
        const int warp = tid >> 5, lane = tid & 31;
        if (lane == 0) { a1[warp] = s1; a2[warp] = s2; }
        sh_pn[tid] = x;          // stash raw x
    }
    __syncthreads();
    {
        float sum  = a1[0] + a1[1] + a1[2] + a1[3];
        float sumq = a2[0] + a2[1] + a2[2] + a2[3];
        const float inv = 1.0f / (float)C_P;
        float mu   = sum * inv;
        float var  = sumq * inv - mu * mu;
        float rstd = rsqrtf(var + 1e-5f);
        __syncthreads();         // everyone sees raw x before overwrite
        if (tid < C_P) {
            float x = sh_pn[tid];
            sh_pn[tid] = (x - mu) * rstd * gamma[tid] + beta[tid];
        }
    }
    __syncthreads();

    // ---- projection: o = tid>>2, t = tid&3; float4 idx f = t + 4u ----
    const int  o = tid >> 2;
    const int  t = tid & 3;
    const int  c = (o < 32) ? o : (o - 32);
    const float* W = (o < 32) ? W1 : W2;

    const float4* w4  = (const float4*)(W + c * C_P);
    const float4* pn4 = (const float4*)sh_pn;
    float acc0 = 0.f, acc1 = 0.f;
    #pragma unroll
    for (int u = 0; u < 8; u += 2) {
        float4 w, v;
        int f0 = t + 4 * u, f1 = t + 4 * (u + 1);
        w = w4[f0]; v = pn4[f0]; acc0 += w.x*v.x + w.y*v.y + w.z*v.z + w.w*v.w;
        w = w4[f1]; v = pn4[f1]; acc1 += w.x*v.x + w.y*v.y + w.z*v.z + w.w*v.w;
    }
    float val = acc0 + acc1;
    val += __shfl_xor_sync(0xFFFFFFFFu, val, 1);
    val += __shfl_xor_sync(0xFFFFFFFFu, val, 2);
    if (t == 0) sh_res[o] = val;
    __syncthreads();

    if (tid < 64) {
        if (tid < 32) {
            // p1 -> A fragments (bf16 hi/lo)
            float v1 = sh_res[tid] + b1[tid];
            uint32_t hu, lu;
            bf16_split(v1, hu, lu);
            uint32_t hu1 = __shfl_down_sync(0xFFFFFFFFu, hu, 1);
            uint32_t lu1 = __shfl_down_sync(0xFFFFFFFFu, lu, 1);
            if ((tid & 1) == 0) {
                const int cch  = tid;
                const int it   = s >> 4;
                const int grow = s & 15;
                const int g    = grow & 7;
                const int top  = grow >> 3;
                const int ks   = cch >> 4;
                const int cl   = cch & 15;
                const int rhi  = cl >> 3;
                const int tt   = (cl & 7) >> 1;
                const int reg  = top + 2 * rhi;
                const int ln   = g * 4 + tt;
                const int i0 = ((((b * 2 + 0) * 2 + ks) * 12 + it) * 32 + ln) * 4 + reg;
                const int i1 = ((((b * 2 + 1) * 2 + ks) * 12 + it) * 32 + ln) * 4 + reg;
                g_p1f[i0] = hu | (hu1 << 16);
                g_p1f[i1] = lu | (lu1 << 16);
            }
        } else {
            float v2 = sh_res[tid] + b2[tid - 32];
            g_p2t[(b * C + (tid - 32)) * SEQ + s] = v2;
        }
    }
}

// ---------------------------------------------------------------------------
// Kernel 3 (fused M-build + MMA). grid = 768 (bk x 3 j-thirds of 64 cols).
// 256 threads, launch_bounds(256,2). A-frags prefetched before M-build.
// Warp tile 48(i) x 32(j): acc[3][4][4] = 48 regs -> no spills.
// ---------------------------------------------------------------------------
__global__ __launch_bounds__(256, 2)
void k3_fused(const float* __restrict__ Wout,
              const float* __restrict__ bout,
              float* __restrict__ out) {
    const int blk    = blockIdx.x;
    const int bk     = blk / 3;
    const int jthird = blk - 3 * bk;
    const int b      = bk >> 7;
    const int k      = bk & (C_I - 1);
    const int tid    = threadIdx.x;
    const int wid    = tid >> 5, lane = tid & 31;
    const int wi     = wid >> 1;                 // 0..3 i-band (48 rows)
    const int wj     = wid & 1;                  // 0..1 j-band (32 cols)

    __shared__ float    shW[C * C];              // 4 KB
    __shared__ uint32_t sB[2 * 2 * 8 * 32 * 2];  // 8 KB fragments (64 cols)

    // stage Wout row k
    ((float4*)shW)[tid] = ((const float4*)(Wout + (size_t)k * C * C))[tid];

    // ---- prefetch ALL A fragments (independent of smem) ----
    uint4 Ah[2][3], Al[2][3];
    {
        const uint4* Af = (const uint4*)g_p1f;
        #pragma unroll
        for (int ks = 0; ks < 2; ++ks)
            #pragma unroll
            for (int itl = 0; itl < 3; ++itl) {
                const int it = wi * 3 + itl;
                Ah[ks][itl] = Af[(((b * 2 + 0) * 2 + ks) * 12 + it) * 32 + lane];
                Al[ks][itl] = Af[(((b * 2 + 1) * 2 + ks) * 12 + it) * 32 + lane];
            }
    }
    __syncthreads();

    // ---- M build: thread = (jloc 0..63, ks 0..1, ch 0..1), 8 c's each ----
    {
        const int jloc = tid & 63;
        const int rest = tid >> 6;
        const int ks   = rest & 1;
        const int ch   = rest >> 1;
        const int j    = jthird * 64 + jloc;
        const float* P2 = g_p2t + (size_t)b * C * SEQ;

        unsigned long long qq[16];
        #pragma unroll
        for (int d2 = 0; d2 < 16; ++d2) {
            float qa = P2[(2 * d2 + 0) * SEQ + j];
            float qb = P2[(2 * d2 + 1) * SEQ + j];
            PACK_F32X2(qq[d2], qa, qb);
        }
        float m[8];
        #pragma unroll
        for (int cc = 0; cc < 8; ++cc) {
            const int c = ks * 16 + ch * 8 + cc;
            const unsigned long long* w2 = (const unsigned long long*)(shW + c * C);
            unsigned long long acc = 0ull;
            #pragma unroll
            for (int d2 = 0; d2 < 16; ++d2)
                FMA_F32X2(acc, qq[d2], w2[d2], acc);
            float lo, hi; UNPACK_F32X2(lo, hi, acc);
            m[cc] = lo + hi;
        }
        // fragment store: jt = jloc/8, g = jloc%8, lane = g*4+t, reg = ch
        const int jt = jloc >> 3;
        const int g  = jloc & 7;
        #pragma unroll
        for (int t = 0; t < 4; ++t) {
            uint32_t h0, l0, h1, l1;
            bf16_split(m[2 * t],     h0, l0);
            bf16_split(m[2 * t + 1], h1, l1);
            const int ln = g * 4 + t;
            sB[((0 * 2 + ks) * 8 + jt) * 64 + ln * 2 + ch] = h0 | (h1 << 16);
            sB[((1 * 2 + ks) * 8 + jt) * 64 + ln * 2 + ch] = l0 | (l1 << 16);
        }
    }
    __syncthreads();

    // ---- MMA ----
    float acc[3][4][4];
    #pragma unroll
    for (int i = 0; i < 3; ++i)
        #pragma unroll
        for (int j = 0; j < 4; ++j)
            #pragma unroll
            for (int q = 0; q < 4; ++q) acc[i][j][q] = 0.0f;

    #pragma unroll
    for (int ks = 0; ks < 2; ++ks) {
        #pragma unroll
        for (int jtl = 0; jtl < 4; ++jtl) {
            const int jt = wj * 4 + jtl;
            uint2 Bh = *(const uint2*)&sB[((0 * 2 + ks) * 8 + jt) * 64 + lane * 2];
            uint2 Bl = *(const uint2*)&sB[((1 * 2 + ks) * 8 + jt) * 64 + lane * 2];
            #pragma unroll
            for (int itl = 0; itl < 3; ++itl) {
                MMA_BF16(acc[itl][jtl], Ah[ks][itl], Bh);
                MMA_BF16(acc[itl][jtl], Ah[ks][itl], Bl);
                MMA_BF16(acc[itl][jtl], Al[ks][itl], Bh);
            }
        }
    }

    // ---- epilogue: (acc + bias) * 0.5 ----
    const float bias = bout[k];
    const int g = lane >> 2, t = lane & 3;
    float* ob = out + (size_t)bk * SEQ * SEQ + jthird * 64;
    #pragma unroll
    for (int itl = 0; itl < 3; ++itl) {
        const int row = (wi * 3 + itl) * 16 + g;
        #pragma unroll
        for (int jtl = 0; jtl < 4; ++jtl) {
            const int col = (wj * 4 + jtl) * 8 + 2 * t;
            float2 v0, v1;
            v0.x = (acc[itl][jtl][0] + bias) * 0.5f;
            v0.y = (acc[itl][jtl][1] + bias) * 0.5f;
            v1.x = (acc[itl][jtl][2] + bias) * 0.5f;
            v1.y = (acc[itl][jtl][3] + bias) * 0.5f;
            *(float2*)(ob + (size_t)row * SEQ + col)       = v0;
            *(float2*)(ob + (size_t)(row + 8) * SEQ + col) = v1;
        }
    }
}

// ---------------------------------------------------------------------------
extern "C" void kernel_launch(void* const* d_in, const int* in_sizes, int n_in,
                              void* d_out, int out_size) {
    const float* p     = (const float*)d_in[0];
    const float* gamma = (const float*)d_in[1];
    const float* beta  = (const float*)d_in[2];
    const float* W1    = (const float*)d_in[3];
    const float* b1    = (const float*)d_in[4];
    const float* W2    = (const float*)d_in[5];
    const float* b2    = (const float*)d_in[6];
    const float* Wout  = (const float*)d_in[7];
    const float* bout  = (const float*)d_in[8];
    float* out = (float*)d_out;

    k1_ln_proj<<<SEQ * BATCH, 256>>>(p, gamma, beta, W1, b1, W2, b2);
    k3_fused<<<BATCH * C_I * 3, 256>>>(Wout, bout, out);
}